// round 14
// baseline (speedup 1.0000x reference)
#include <cuda_runtime.h>
#include <cstddef>

// CAN: per-sample 2-layer MLP, B=16384, N=50, D=16, fp32.
// x = relu(x @ W0 + b0); x = relu(x @ W1 + b1)
//
// R13: lane owns 5 rows x ALL 16 cols (10 lanes/sample). x read straight
// from global (LDG.128, each byte once); layer-0 output kept in registers
// as packed f32x2 (40 ull); layer-1 done in 4 quarter-column passes reading
// W from smem, storing straight to global. Only W is staged in shared.
// No STS, no syncwarp, minimal LSU ops.

#define CAN_D 16
#define CAN_N 50
#define SPB 16                // samples per block
#define TPB 160               // 16 samples * 10 lanes
#define W_FLOATS 544
#define W_STRIDE 552          // /4=138 float4; 138 mod 8 = 2 -> samples in
                              // a warp hit distinct bank groups {0,2,4,6}

typedef unsigned long long ull;

#define FMA2(acc, x2, w2) \
    asm("fma.rn.f32x2 %0, %1, %2, %3;" : "=l"(acc) : "l"(x2), "l"(w2), "l"(acc))

__device__ __forceinline__ ull pack2(float a, float b) {
    ull r; asm("mov.b64 %0, {%1, %2};" : "=l"(r) : "f"(a), "f"(b)); return r;
}
__device__ __forceinline__ ull splat2(float a) {
    ull r; asm("mov.b64 %0, {%1, %1};" : "=l"(r) : "f"(a)); return r;
}
__device__ __forceinline__ void unpack2(ull p, float& lo, float& hi) {
    asm("mov.b64 {%0, %1}, %2;" : "=f"(lo), "=f"(hi) : "l"(p));
}
__device__ __forceinline__ void cp_async16(unsigned dst, const void* src) {
    asm volatile("cp.async.cg.shared.global [%0], [%1], 16;"
                 :: "r"(dst), "l"(src));
}

__global__ __launch_bounds__(TPB, 3)
void can_kernel(const float* __restrict__ user,
                const float* __restrict__ item,
                float* __restrict__ out,
                int B)
{
    __shared__ __align__(16) float ws[SPB * W_STRIDE];   // 35.3 KB

    const int tid   = threadIdx.x;
    const int sbase = blockIdx.x * SPB;
    const int nsamp = min(SPB, B - sbase);
    const int nw4   = nsamp * 136;                        // <= 2176

    // ---- stage W only, via cp.async ----
    {
        const float4* __restrict__ gw =
            reinterpret_cast<const float4*>(item + (size_t)sbase * W_FLOATS);
        #pragma unroll
        for (int k = 0; k < 14; ++k) {
            int i = tid + k * TPB;
            if (i < nw4) {
                int s = i / 136, f = i - s * 136;
                unsigned dst = (unsigned)__cvta_generic_to_shared(
                    ws + s * W_STRIDE + f * 4);
                cp_async16(dst, gw + i);
            }
        }
        asm volatile("cp.async.commit_group;" ::: "memory");
        asm volatile("cp.async.wait_group 0;"  ::: "memory");
    }
    __syncthreads();

    const int sl = tid / 10;        // local sample
    const int rg = tid - sl * 10;   // row group: rows rg*5 .. rg*5+4
    if (sl >= nsamp) return;

    const float4* __restrict__ wl =
        reinterpret_cast<const float4*>(ws + sl * W_STRIDE);      // layer 0
    const float4* __restrict__ wl1 = wl + 68;                     // layer 1
    const float* __restrict__ gx =
        user + (size_t)(sbase + sl) * (CAN_N * CAN_D) + rg * 5 * CAN_D;

    // ================= layer 0: acc = x @ W0 + b0, packed pairs =============
    ull a0[5][8];    // 5 rows x 16 cols as 8 f32x2 pairs (80 regs)
    {
        float4 b0 = wl[64], b1 = wl[65], b2 = wl[66], b3 = wl[67];
        ull bb0 = pack2(b0.x, b0.y), bb1 = pack2(b0.z, b0.w);
        ull bb2 = pack2(b1.x, b1.y), bb3 = pack2(b1.z, b1.w);
        ull bb4 = pack2(b2.x, b2.y), bb5 = pack2(b2.z, b2.w);
        ull bb6 = pack2(b3.x, b3.y), bb7 = pack2(b3.z, b3.w);
        #pragma unroll
        for (int r = 0; r < 5; ++r) {
            a0[r][0] = bb0; a0[r][1] = bb1; a0[r][2] = bb2; a0[r][3] = bb3;
            a0[r][4] = bb4; a0[r][5] = bb5; a0[r][6] = bb6; a0[r][7] = bb7;
        }
    }
    #pragma unroll
    for (int dc = 0; dc < 4; ++dc) {
        // x chunk: 5 rows x 4 d's (5 LDG.128; L1-hits for dc>0)
        float4 xr[5];
        #pragma unroll
        for (int r = 0; r < 5; ++r)
            xr[r] = *reinterpret_cast<const float4*>(gx + r * CAN_D + dc * 4);
        #pragma unroll
        for (int k = 0; k < 4; ++k) {
            const int d = 4 * dc + k;
            float4 wA = wl[4 * d + 0], wB = wl[4 * d + 1];
            float4 wC = wl[4 * d + 2], wD = wl[4 * d + 3];
            ull w0 = pack2(wA.x, wA.y), w1 = pack2(wA.z, wA.w);
            ull w2 = pack2(wB.x, wB.y), w3 = pack2(wB.z, wB.w);
            ull w4 = pack2(wC.x, wC.y), w5 = pack2(wC.z, wC.w);
            ull w6 = pack2(wD.x, wD.y), w7 = pack2(wD.z, wD.w);
            #pragma unroll
            for (int r = 0; r < 5; ++r) {
                float xv = (k == 0) ? xr[r].x : (k == 1) ? xr[r].y
                         : (k == 2) ? xr[r].z : xr[r].w;
                ull px = splat2(xv);
                FMA2(a0[r][0], px, w0); FMA2(a0[r][1], px, w1);
                FMA2(a0[r][2], px, w2); FMA2(a0[r][3], px, w3);
                FMA2(a0[r][4], px, w4); FMA2(a0[r][5], px, w5);
                FMA2(a0[r][6], px, w6); FMA2(a0[r][7], px, w7);
            }
        }
    }
    // relu in place (packed)
    #pragma unroll
    for (int r = 0; r < 5; ++r)
        #pragma unroll
        for (int j = 0; j < 8; ++j) {
            float lo, hi;
            unpack2(a0[r][j], lo, hi);
            a0[r][j] = pack2(fmaxf(lo, 0.f), fmaxf(hi, 0.f));
        }

    // ========== layer 1: 4 quarter-column passes, store to global ===========
    float* __restrict__ go =
        out + (size_t)(sbase + sl) * (CAN_N * CAN_D) + rg * 5 * CAN_D;
    #pragma unroll
    for (int q = 0; q < 4; ++q) {
        ull c[5][2];
        {
            float4 bq = wl1[64 + q];
            ull cb0 = pack2(bq.x, bq.y), cb1 = pack2(bq.z, bq.w);
            #pragma unroll
            for (int r = 0; r < 5; ++r) { c[r][0] = cb0; c[r][1] = cb1; }
        }
        #pragma unroll
        for (int dp = 0; dp < 8; ++dp) {        // d pair (2dp, 2dp+1)
            float4 wq0 = wl1[4 * (2 * dp)     + q];
            float4 wq1 = wl1[4 * (2 * dp + 1) + q];
            ull u0 = pack2(wq0.x, wq0.y), u1 = pack2(wq0.z, wq0.w);
            ull v0 = pack2(wq1.x, wq1.y), v1 = pack2(wq1.z, wq1.w);
            #pragma unroll
            for (int r = 0; r < 5; ++r) {
                float e0, e1;
                unpack2(a0[r][dp], e0, e1);
                ull p0 = splat2(e0), p1 = splat2(e1);
                FMA2(c[r][0], p0, u0); FMA2(c[r][1], p0, u1);
                FMA2(c[r][0], p1, v0); FMA2(c[r][1], p1, v1);
            }
        }
        #pragma unroll
        for (int r = 0; r < 5; ++r) {
            float f0, f1, f2, f3;
            unpack2(c[r][0], f0, f1);
            unpack2(c[r][1], f2, f3);
            *reinterpret_cast<float4*>(go + r * CAN_D + q * 4) =
                make_float4(fmaxf(f0, 0.f), fmaxf(f1, 0.f),
                            fmaxf(f2, 0.f), fmaxf(f3, 0.f));
        }
    }
}

extern "C" void kernel_launch(void* const* d_in, const int* in_sizes, int n_in,
                              void* d_out, int out_size)
{
    const float* user = (const float*)d_in[0];
    const float* item = (const float*)d_in[1];
    float* out = (float*)d_out;

    const int B = in_sizes[0] / (CAN_N * CAN_D);   // 16384
    const int grid = (B + SPB - 1) / SPB;

    can_kernel<<<grid, TPB>>>(user, item, out, B);
}